// round 14
// baseline (speedup 1.0000x reference)
#include <cuda_runtime.h>
#include <cuda_fp16.h>
#include <cstdint>
#include <math.h>

#define DM 1024
#define DS 16
#define NB 4096
#define NBC 32768

#define BM 128
#define BN 128
#define BK 32
#define NSTG 4
#define NTHREADS 128
#define A_STAGE (BM * BK * 2)                 // 8192 B
#define B_STAGE (BN * BK * 2)                 // 8192 B
#define STAGE_BYTES (A_STAGE + B_STAGE)       // 16384
#define SMEM_BYTES (NSTG * STAGE_BYTES)       // 65536 -> 2 CTAs/SM

// ---------------- scratch (device globals) ---------------------------------
__device__ __half g_xh [NB * DM];
__device__ __half g_w1h[DM * DM];
__device__ __half g_w2h[DM * DM];
__device__ __half g_woh[DM * DM];
__device__ __half g_wbch[NBC * DM];
__device__ __half g_zh [NB * DM];
__device__ float  g_u  [NB * DM];
__device__ float  g_dt [NB * DM];
__device__ float  g_An [DM * DS];

// ---------------- helpers ---------------------------------------------------
__device__ __forceinline__ uint32_t smem_u32(const void* p) {
    uint32_t a;
    asm("{ .reg .u64 t; cvta.to.shared.u64 t, %1; cvt.u32.u64 %0, t; }" : "=r"(a) : "l"(p));
    return a;
}
__device__ __forceinline__ void cpa16(uint32_t s, const void* g) {
    asm volatile("cp.async.cg.shared.global [%0], [%1], 16;" :: "r"(s), "l"(g));
}
__device__ __forceinline__ float softplus_f(float x) {
    return x > 20.f ? x : log1pf(__expf(x));
}

#define LDSM4(r0, r1, r2, r3, addr)                                          \
    asm volatile("ldmatrix.sync.aligned.m8n8.x4.shared.b16 {%0,%1,%2,%3}, [%4];" \
        : "=r"(r0), "=r"(r1), "=r"(r2), "=r"(r3) : "r"(addr))

__device__ __forceinline__ void mma16(float* d, uint32_t a0, uint32_t a1,
                                      uint32_t a2, uint32_t a3,
                                      uint32_t b0, uint32_t b1) {
    asm volatile(
        "mma.sync.aligned.m16n8k16.row.col.f32.f16.f16.f32 "
        "{%0,%1,%2,%3}, {%4,%5,%6,%7}, {%8,%9}, {%0,%1,%2,%3};"
        : "+f"(d[0]), "+f"(d[1]), "+f"(d[2]), "+f"(d[3])
        : "r"(a0), "r"(a1), "r"(a2), "r"(a3), "r"(b0), "r"(b1));
}

// ---------------- gmem(fp16) -> smem stage, XOR-swizzled --------------------
// Row-local r (0..127), 64B/row (32 fp16); 16B column c swizzled
// c ^= (r>>1)&3 -> ldmatrix phases conflict-free.
__device__ __forceinline__ void stage_load(const __half* __restrict__ A,
                                           const __half* __restrict__ W, int K,
                                           int bm, int bn, int chunk,
                                           uint32_t sbase, int tid) {
    const int kt = chunk * BK;
#pragma unroll
    for (int i = 0; i < 4; i++) {
        int id = tid + i * NTHREADS;       // 0..511
        int row = id >> 2, c = id & 3;
        cpa16(sbase + row * 64 + ((c ^ ((row >> 1) & 3)) << 4),
              A + (size_t)(bm + row) * K + kt + c * 8);
    }
#pragma unroll
    for (int i = 0; i < 4; i++) {
        int id = tid + i * NTHREADS;
        int row = id >> 2, c = id & 3;
        cpa16(sbase + A_STAGE + row * 64 + ((c ^ ((row >> 1) & 3)) << 4),
              W + (size_t)(bn + row) * K + kt + c * 8);
    }
    asm volatile("cp.async.commit_group;" ::: "memory");
}

// ---------------- fp16 mma mainloop (explicit 2-step frag preload) ----------
// 128 threads, warp grid 2(M) x 2(N), warp tile 64x64.
// Per chunk: 16 LDSM.x4 (both k16 steps) issued up front, then 64 MMAs —
// the second step's loads hide under the first step's MMAs.
__device__ __forceinline__ void gemm_mainloop(const __half* __restrict__ A,
                                              const __half* __restrict__ W, int K,
                                              int bm, int bn, uint32_t smem_base,
                                              float acc[4][8][4]) {
    const int tid  = threadIdx.x;
    const int lane = tid & 31, wid = tid >> 5;
    const int wm = wid >> 1, wn = wid & 1;

    const int arl = lane & 15;                  // A row within 16-row tile
    const int acd = lane >> 4;                  // A k16-half select
    const int asw = (arl >> 1) & 3;
    const uint32_t ca[2] = { (uint32_t)(((0 + acd) ^ asw) << 4),
                             (uint32_t)(((2 + acd) ^ asw) << 4) };
    const int brl = (lane & 7) | ((lane >> 4) << 3);   // B row
    const int bcd = (lane >> 3) & 1;
    const int bsw = (brl >> 1) & 3;
    const uint32_t cb[2] = { (uint32_t)(((0 + bcd) ^ bsw) << 4),
                             (uint32_t)(((2 + bcd) ^ bsw) << 4) };

#pragma unroll
    for (int mt = 0; mt < 4; mt++)
#pragma unroll
        for (int nt = 0; nt < 8; nt++)
#pragma unroll
            for (int r = 0; r < 4; r++) acc[mt][nt][r] = 0.f;

    const int nch = K / BK;
#pragma unroll 1
    for (int s = 0; s < NSTG - 1; s++)
        stage_load(A, W, K, bm, bn, s, smem_base + s * STAGE_BYTES, tid);

#pragma unroll 1
    for (int i = 0; i < nch; i++) {
        if (i < nch - 1)
            asm volatile("cp.async.wait_group 2;" ::: "memory");
        else
            asm volatile("cp.async.wait_group 0;" ::: "memory");
        __syncthreads();
        const int nx = i + NSTG - 1;
        if (nx < nch)
            stage_load(A, W, K, bm, bn, nx, smem_base + (nx & (NSTG - 1)) * STAGE_BYTES, tid);

        const uint32_t st    = smem_base + (i & (NSTG - 1)) * STAGE_BYTES;
        const uint32_t abase = st + (wm * 64 + arl) * 64;
        const uint32_t bbase = st + A_STAGE + (wn * 64 + brl) * 64;

        uint32_t af[2][4][4], bf[2][8][2];
#pragma unroll
        for (int s2 = 0; s2 < 2; s2++) {        // all frags for both steps
#pragma unroll
            for (int mt = 0; mt < 4; mt++)
                LDSM4(af[s2][mt][0], af[s2][mt][1], af[s2][mt][2], af[s2][mt][3],
                      abase + mt * 1024 + ca[s2]);
#pragma unroll
            for (int pr = 0; pr < 4; pr++)
                LDSM4(bf[s2][2 * pr][0], bf[s2][2 * pr][1],
                      bf[s2][2 * pr + 1][0], bf[s2][2 * pr + 1][1],
                      bbase + pr * 1024 + cb[s2]);
        }
#pragma unroll
        for (int s2 = 0; s2 < 2; s2++)
#pragma unroll
            for (int mt = 0; mt < 4; mt++)
#pragma unroll
                for (int nt = 0; nt < 8; nt++)
                    mma16(acc[mt][nt], af[s2][mt][0], af[s2][mt][1],
                          af[s2][mt][2], af[s2][mt][3],
                          bf[s2][nt][0], bf[s2][nt][1]);
    }
}

// ---------------- generic epilogue store (m64n64 mapping) -------------------
template <int EPI>   // 0=none, 1=softplus(v+bias), 2=v+bias
__device__ __forceinline__ void gemm_epilogue(float acc[4][8][4],
                                              const float* __restrict__ bias,
                                              float* __restrict__ Out,
                                              int bm, int bn, int N) {
    const int lane = threadIdx.x & 31, wid = threadIdx.x >> 5;
    const int wm = wid >> 1, wn = wid & 1;
    const int q = lane >> 2, c = lane & 3;

#pragma unroll
    for (int mt = 0; mt < 4; mt++) {
        const int row0 = bm + wm * 64 + mt * 16 + q;
#pragma unroll
        for (int nt = 0; nt < 8; nt++) {
            const int col = bn + wn * 64 + nt * 8 + 2 * c;
            float2 v0 = make_float2(acc[mt][nt][0], acc[mt][nt][1]);
            float2 v1 = make_float2(acc[mt][nt][2], acc[mt][nt][3]);
            if (EPI == 1) {
                const float2 b2 = *(const float2*)(bias + col);
                v0.x = softplus_f(v0.x + b2.x); v0.y = softplus_f(v0.y + b2.y);
                v1.x = softplus_f(v1.x + b2.x); v1.y = softplus_f(v1.y + b2.y);
            } else if (EPI == 2) {
                const float2 b2 = *(const float2*)(bias + col);
                v0.x += b2.x; v0.y += b2.y; v1.x += b2.x; v1.y += b2.y;
            }
            *(float2*)(Out + (size_t)row0 * N + col)       = v0;
            *(float2*)(Out + (size_t)(row0 + 8) * N + col) = v1;
        }
    }
}

// ---------------- fused u/dt GEMM + bc weight conversion --------------------
// blocks [0,512): GEMM  (b%32 -> bm tile; b/32 in [0,8) -> W1/u, [8,16) -> W2/dt)
// blocks [512, 512+512): convert bc_w -> g_wbch.
// Each conversion block covers 128 iters * 128 thr = 16384 float4 = 65536
// floats; 512 blocks * 65536 = 33,554,432 = NBC*DM exactly.
#define PREP_BC_BLOCKS 512
__global__ void __launch_bounds__(NTHREADS, 2)
gemm_dual(const __half* __restrict__ Xh, const __half* __restrict__ W1,
          const __half* __restrict__ W2, const float* __restrict__ dt_b,
          const float* __restrict__ bc_w)
{
    extern __shared__ __align__(128) char smem[];
    const int b = blockIdx.x;
    if (b < 512) {
        const int bm = (b & 31) * BM;
        const int yy = b >> 5;
        const int bn = (yy & 7) * BN;
        float acc[4][8][4];
        if (yy < 8) {
            gemm_mainloop(Xh, W1, DM, bm, bn, smem_u32(smem), acc);
            gemm_epilogue<0>(acc, nullptr, g_u, bm, bn, DM);
        } else {
            gemm_mainloop(Xh, W2, DM, bm, bn, smem_u32(smem), acc);
            gemm_epilogue<1>(acc, dt_b, g_dt, bm, bn, DM);
        }
    } else {
        // bc weight fp32 -> fp16 (fills SMs as GEMM waves drain)
        const int pb = b - 512;
        const int base = pb * 16384;                 // float4 units
#pragma unroll 4
        for (int k = 0; k < 128; k++) {
            const int i = (base + k * NTHREADS + threadIdx.x) * 4;
            float4 v = *(const float4*)(bc_w + i);
            __half2* dp = (__half2*)(g_wbch + i);
            dp[0] = __floats2half2_rn(v.x, v.y);
            dp[1] = __floats2half2_rn(v.z, v.w);
        }
    }
}

// ---------------- out projection GEMM ---------------------------------------
__global__ void __launch_bounds__(NTHREADS, 2)
gemm_out(const __half* __restrict__ Zh, const __half* __restrict__ Wo,
         const float* __restrict__ out_b, float* __restrict__ Out)
{
    extern __shared__ __align__(128) char smem[];
    const int bm = blockIdx.x * BM, bn = blockIdx.y * BN;
    float acc[4][8][4];
    gemm_mainloop(Zh, Wo, DM, bm, bn, smem_u32(smem), acc);
    gemm_epilogue<2>(acc, out_b, Out, bm, bn, DM);
}

// ---------------- fused bc GEMM + SSM state update --------------------------
// Each warp's 64 N-cols = TWO d-channels: nt 0-3 -> ch 0, nt 4-7 -> ch 1.
__global__ void __launch_bounds__(NTHREADS, 2)
mamba_tc(const __half* __restrict__ A, const __half* __restrict__ W,
         const float* __restrict__ H, const float* __restrict__ Dp,
         float* __restrict__ Hout)
{
    extern __shared__ __align__(128) char smem[];
    const int bm = blockIdx.x * BM, bn = blockIdx.y * BN;
    float acc[4][8][4];
    gemm_mainloop(A, W, DM, bm, bn, smem_u32(smem), acc);

    const int lane = threadIdx.x & 31, wid = threadIdx.x >> 5;
    const int wm = wid >> 1, wn = wid & 1;
    const int q = lane >> 2, c = lane & 3;
    const int s0 = 2 * c;

#pragma unroll
    for (int ch = 0; ch < 2; ch++) {
        const int dg = (bn >> 5) + wn * 2 + ch;
        const int nb0 = 4 * ch;

        const float An0 = g_An[dg * DS + s0],     An1 = g_An[dg * DS + s0 + 1];
        const float An2 = g_An[dg * DS + s0 + 8], An3 = g_An[dg * DS + s0 + 9];
        const float dc = Dp[dg];

#pragma unroll
        for (int mt = 0; mt < 4; mt++) {
#pragma unroll
            for (int hf = 0; hf < 2; hf++) {
                const int bg = bm + wm * 64 + mt * 16 + q + 8 * hf;
                const float u  = g_u [(size_t)bg * DM + dg];
                const float dt = g_dt[(size_t)bg * DM + dg];
                const float Bv0 = acc[mt][nb0 + 0][2 * hf], Bv1 = acc[mt][nb0 + 0][2 * hf + 1];
                const float Bv2 = acc[mt][nb0 + 1][2 * hf], Bv3 = acc[mt][nb0 + 1][2 * hf + 1];
                const float Cv0 = acc[mt][nb0 + 2][2 * hf], Cv1 = acc[mt][nb0 + 2][2 * hf + 1];
                const float Cv2 = acc[mt][nb0 + 3][2 * hf], Cv3 = acc[mt][nb0 + 3][2 * hf + 1];

                const float* hp = H + ((size_t)bg * DM + dg) * DS;
                const float2 ha = *(const float2*)(hp + s0);
                const float2 hb = *(const float2*)(hp + 8 + s0);

                const float du = dt * u;
                const float h0 = __expf(dt * An0) * ha.x + du * Bv0;
                const float h1 = __expf(dt * An1) * ha.y + du * Bv1;
                const float h2 = __expf(dt * An2) * hb.x + du * Bv2;
                const float h3 = __expf(dt * An3) * hb.y + du * Bv3;

                float* ho = Hout + ((size_t)bg * DM + dg) * DS;
                *(float2*)(ho + s0)     = make_float2(h0, h1);
                *(float2*)(ho + 8 + s0) = make_float2(h2, h3);

                float y = h0 * Cv0 + h1 * Cv1 + h2 * Cv2 + h3 * Cv3;
                y += __shfl_xor_sync(0xffffffffu, y, 1);
                y += __shfl_xor_sync(0xffffffffu, y, 2);
                if (c == 0) {
                    y = fmaf(dc, u, y);
                    const float z = y / (1.f + __expf(-y));
                    g_zh[(size_t)bg * DM + dg] = __float2half_rn(z);
                }
            }
        }
    }
}

// ---------------- prep1: x + square weights + A -----------------------------
// Blocks: [0,4096) x ; [4096,5120) w1 ; [5120,6144) w2 ; [6144,7168) wo ;
// [7168,7232) A_log.
#define PB_X (NB * DM / 1024)        // 4096
#define PB_W (DM * DM / 1024)        // 1024

__device__ __forceinline__ void cvt4(const float* __restrict__ s,
                                     __half* __restrict__ d, int i) {
    float4 v = *(const float4*)(s + i);
    __half2* dp = (__half2*)(d + i);
    dp[0] = __floats2half2_rn(v.x, v.y);
    dp[1] = __floats2half2_rn(v.z, v.w);
}
__global__ void prep1(const float* __restrict__ x,
                      const float* __restrict__ w1,
                      const float* __restrict__ w2,
                      const float* __restrict__ wo,
                      const float* __restrict__ A_log) {
    int b = blockIdx.x;
    if (b < PB_X) {
        cvt4(x, g_xh, (b * 256 + threadIdx.x) * 4);
    } else if (b < PB_X + PB_W) {
        cvt4(w1, g_w1h, ((b - PB_X) * 256 + threadIdx.x) * 4);
    } else if (b < PB_X + 2 * PB_W) {
        cvt4(w2, g_w2h, ((b - PB_X - PB_W) * 256 + threadIdx.x) * 4);
    } else if (b < PB_X + 3 * PB_W) {
        cvt4(wo, g_woh, ((b - PB_X - 2 * PB_W) * 256 + threadIdx.x) * 4);
    } else {
        int i = (b - PB_X - 3 * PB_W) * 256 + threadIdx.x;
        if (i < DM * DS) g_An[i] = -__expf(A_log[i]);
    }
}

// ---------------- launch -----------------------------------------------------
extern "C" void kernel_launch(void* const* d_in, const int* in_sizes, int n_in,
                              void* d_out, int out_size)
{
    const float* x     = (const float*)d_in[0];
    const float* h     = (const float*)d_in[1];
    const float* in_w  = (const float*)d_in[2];
    const float* dt_w  = (const float*)d_in[3];
    const float* dt_b  = (const float*)d_in[4];
    const float* bc_w  = (const float*)d_in[5];
    const float* A_log = (const float*)d_in[6];
    const float* Dp    = (const float*)d_in[7];
    const float* out_w = (const float*)d_in[8];
    const float* out_b = (const float*)d_in[9];

    float* out  = (float*)d_out;
    float* hout = out + (size_t)NB * DM;

    __half *p_xh, *p_w1, *p_w2, *p_wo, *p_wbc, *p_zh;
    cudaGetSymbolAddress((void**)&p_xh,  g_xh);
    cudaGetSymbolAddress((void**)&p_w1,  g_w1h);
    cudaGetSymbolAddress((void**)&p_w2,  g_w2h);
    cudaGetSymbolAddress((void**)&p_wo,  g_woh);
    cudaGetSymbolAddress((void**)&p_wbc, g_wbch);
    cudaGetSymbolAddress((void**)&p_zh,  g_zh);

    cudaFuncSetAttribute(gemm_dual, cudaFuncAttributeMaxDynamicSharedMemorySize, SMEM_BYTES);
    cudaFuncSetAttribute(gemm_out,  cudaFuncAttributeMaxDynamicSharedMemorySize, SMEM_BYTES);
    cudaFuncSetAttribute(mamba_tc,  cudaFuncAttributeMaxDynamicSharedMemorySize, SMEM_BYTES);

    // L1: x + square weights + A
    prep1<<<PB_X + 3 * PB_W + 64, 256>>>(x, in_w, dt_w, out_w, A_log);

    // L2: u/dt GEMMs + bc weight conversion in one launch
    gemm_dual<<<512 + PREP_BC_BLOCKS, NTHREADS, SMEM_BYTES>>>(p_xh, p_w1, p_w2, dt_b, bc_w);

    // L3: fused bc GEMM + SSM update
    dim3 gbc(NB / BM, NBC / BN);         // (32, 256)
    mamba_tc<<<gbc, NTHREADS, SMEM_BYTES>>>(p_xh, p_wbc, h, Dp, hout);

    // L4: out projection
    dim3 gsq(NB / BM, DM / BN);          // (32, 8)
    gemm_out<<<gsq, NTHREADS, SMEM_BYTES>>>(p_zh, p_wo, out_b, out);
}

// round 15
// speedup vs baseline: 1.0488x; 1.0488x over previous
#include <cuda_runtime.h>
#include <cuda_fp16.h>
#include <cstdint>
#include <math.h>

#define DM 1024
#define DS 16
#define NB 4096
#define NBC 32768

#define BM 128
#define BN 128
#define BK 32
#define NSTG 4
#define NTHREADS 256
#define A_STAGE (BM * BK * 2)                 // 8192 B
#define B_STAGE (BN * BK * 2)                 // 8192 B
#define STAGE_BYTES (A_STAGE + B_STAGE)       // 16384
#define SMEM_BYTES (NSTG * STAGE_BYTES)       // 65536 -> 2 CTAs/SM

// ---------------- scratch (device globals) ---------------------------------
__device__ __half g_xh [NB * DM];
__device__ __half g_w1h[DM * DM];
__device__ __half g_w2h[DM * DM];
__device__ __half g_woh[DM * DM];
__device__ __half g_wbch[NBC * DM];
__device__ __half g_zh [NB * DM];
__device__ float  g_u  [NB * DM];
__device__ float  g_dt [NB * DM];
__device__ float  g_An [DM * DS];

// ---------------- helpers ---------------------------------------------------
__device__ __forceinline__ uint32_t smem_u32(const void* p) {
    uint32_t a;
    asm("{ .reg .u64 t; cvta.to.shared.u64 t, %1; cvt.u32.u64 %0, t; }" : "=r"(a) : "l"(p));
    return a;
}
__device__ __forceinline__ void cpa16(uint32_t s, const void* g) {
    asm volatile("cp.async.cg.shared.global [%0], [%1], 16;" :: "r"(s), "l"(g));
}
__device__ __forceinline__ float softplus_f(float x) {
    return x > 20.f ? x : log1pf(__expf(x));
}

#define LDSM4(r0, r1, r2, r3, addr)                                          \
    asm volatile("ldmatrix.sync.aligned.m8n8.x4.shared.b16 {%0,%1,%2,%3}, [%4];" \
        : "=r"(r0), "=r"(r1), "=r"(r2), "=r"(r3) : "r"(addr))

__device__ __forceinline__ void mma16(float* d, uint32_t a0, uint32_t a1,
                                      uint32_t a2, uint32_t a3,
                                      uint32_t b0, uint32_t b1) {
    asm volatile(
        "mma.sync.aligned.m16n8k16.row.col.f32.f16.f16.f32 "
        "{%0,%1,%2,%3}, {%4,%5,%6,%7}, {%8,%9}, {%0,%1,%2,%3};"
        : "+f"(d[0]), "+f"(d[1]), "+f"(d[2]), "+f"(d[3])
        : "r"(a0), "r"(a1), "r"(a2), "r"(a3), "r"(b0), "r"(b1));
}

// ---------------- gmem(fp16) -> smem stage, XOR-swizzled --------------------
// Row-local r (0..127), 64B/row (32 fp16); 16B column c swizzled
// c ^= (r>>1)&3 -> ldmatrix phases conflict-free.
__device__ __forceinline__ void stage_load(const __half* __restrict__ A,
                                           const __half* __restrict__ W, int K,
                                           int bm, int bn, int chunk,
                                           uint32_t sbase, int tid) {
    const int kt = chunk * BK;
#pragma unroll
    for (int i = 0; i < 2; i++) {
        int id = tid + i * NTHREADS;       // 0..511
        int row = id >> 2, c = id & 3;
        cpa16(sbase + row * 64 + ((c ^ ((row >> 1) & 3)) << 4),
              A + (size_t)(bm + row) * K + kt + c * 8);
    }
#pragma unroll
    for (int i = 0; i < 2; i++) {
        int id = tid + i * NTHREADS;
        int row = id >> 2, c = id & 3;
        cpa16(sbase + A_STAGE + row * 64 + ((c ^ ((row >> 1) & 3)) << 4),
              W + (size_t)(bn + row) * K + kt + c * 8);
    }
    asm volatile("cp.async.commit_group;" ::: "memory");
}

// ---------------- fp16 mma mainloop (R9 config: compiler-scheduled) ---------
// 256 threads, warp grid 2(M) x 4(N), warp tile 64x32.
__device__ __forceinline__ void gemm_mainloop(const __half* __restrict__ A,
                                              const __half* __restrict__ W, int K,
                                              int bm, int bn, uint32_t smem_base,
                                              float acc[4][4][4]) {
    const int tid  = threadIdx.x;
    const int lane = tid & 31, wid = tid >> 5;
    const int wm = wid >> 2, wn = wid & 3;

    const int arl = lane & 15;                  // A row within 16-row tile
    const int acd = lane >> 4;                  // A k16-half select
    const int asw = (arl >> 1) & 3;
    const uint32_t ca[2] = { (uint32_t)(((0 + acd) ^ asw) << 4),
                             (uint32_t)(((2 + acd) ^ asw) << 4) };
    const int brl = (lane & 7) | ((lane >> 4) << 3);   // B row
    const int bcd = (lane >> 3) & 1;
    const int bsw = (brl >> 1) & 3;
    const uint32_t cb[2] = { (uint32_t)(((0 + bcd) ^ bsw) << 4),
                             (uint32_t)(((2 + bcd) ^ bsw) << 4) };

#pragma unroll
    for (int mt = 0; mt < 4; mt++)
#pragma unroll
        for (int nt = 0; nt < 4; nt++)
#pragma unroll
            for (int r = 0; r < 4; r++) acc[mt][nt][r] = 0.f;

    const int nch = K / BK;
#pragma unroll 1
    for (int s = 0; s < NSTG - 1; s++)
        stage_load(A, W, K, bm, bn, s, smem_base + s * STAGE_BYTES, tid);

#pragma unroll 1
    for (int i = 0; i < nch; i++) {
        if (i < nch - 1)
            asm volatile("cp.async.wait_group 2;" ::: "memory");
        else
            asm volatile("cp.async.wait_group 0;" ::: "memory");
        __syncthreads();
        const int nx = i + NSTG - 1;
        if (nx < nch)
            stage_load(A, W, K, bm, bn, nx, smem_base + (nx & (NSTG - 1)) * STAGE_BYTES, tid);

        const uint32_t st    = smem_base + (i & (NSTG - 1)) * STAGE_BYTES;
        const uint32_t abase = st + (wm * 64 + arl) * 64;
        const uint32_t bbase = st + A_STAGE + (wn * 32 + brl) * 64;

#pragma unroll
        for (int s2 = 0; s2 < 2; s2++) {        // two k16 steps per BK=32
            uint32_t af[4][4], bf[4][2];
#pragma unroll
            for (int mt = 0; mt < 4; mt++)
                LDSM4(af[mt][0], af[mt][1], af[mt][2], af[mt][3],
                      abase + mt * 1024 + ca[s2]);
#pragma unroll
            for (int pr = 0; pr < 2; pr++)
                LDSM4(bf[2 * pr][0], bf[2 * pr][1], bf[2 * pr + 1][0], bf[2 * pr + 1][1],
                      bbase + pr * 1024 + cb[s2]);
#pragma unroll
            for (int mt = 0; mt < 4; mt++)
#pragma unroll
                for (int nt = 0; nt < 4; nt++)
                    mma16(acc[mt][nt], af[mt][0], af[mt][1], af[mt][2], af[mt][3],
                          bf[nt][0], bf[nt][1]);
        }
    }
}

// ---------------- generic epilogue store ------------------------------------
template <int EPI>   // 0=none, 1=softplus(v+bias), 2=v+bias
__device__ __forceinline__ void gemm_epilogue(float acc[4][4][4],
                                              const float* __restrict__ bias,
                                              float* __restrict__ Out,
                                              int bm, int bn, int N) {
    const int lane = threadIdx.x & 31, wid = threadIdx.x >> 5;
    const int wm = wid >> 2, wn = wid & 3;
    const int q = lane >> 2, c = lane & 3;

#pragma unroll
    for (int mt = 0; mt < 4; mt++) {
        const int row0 = bm + wm * 64 + mt * 16 + q;
#pragma unroll
        for (int nt = 0; nt < 4; nt++) {
            const int col = bn + wn * 32 + nt * 8 + 2 * c;
            float2 v0 = make_float2(acc[mt][nt][0], acc[mt][nt][1]);
            float2 v1 = make_float2(acc[mt][nt][2], acc[mt][nt][3]);
            if (EPI == 1) {
                const float2 b2 = *(const float2*)(bias + col);
                v0.x = softplus_f(v0.x + b2.x); v0.y = softplus_f(v0.y + b2.y);
                v1.x = softplus_f(v1.x + b2.x); v1.y = softplus_f(v1.y + b2.y);
            } else if (EPI == 2) {
                const float2 b2 = *(const float2*)(bias + col);
                v0.x += b2.x; v0.y += b2.y; v1.x += b2.x; v1.y += b2.y;
            }
            *(float2*)(Out + (size_t)row0 * N + col)       = v0;
            *(float2*)(Out + (size_t)(row0 + 8) * N + col) = v1;
        }
    }
}

// ---------------- fused u/dt GEMM + bc weight conversion --------------------
// blocks [0,512): GEMM  (b&31 -> bm tile; b>>5 in [0,8) -> W1/u, [8,16) -> W2/dt)
// blocks [512,1024): convert bc_w -> g_wbch.
// Conversion block: 64 iters * 256 thr * float4 = 65536 floats;
// 512 blocks * 65536 = 33,554,432 = NBC*DM exactly.
#define PREP_BC_BLOCKS 512
__global__ void __launch_bounds__(NTHREADS, 2)
gemm_dual(const __half* __restrict__ Xh, const __half* __restrict__ W1,
          const __half* __restrict__ W2, const float* __restrict__ dt_b,
          const float* __restrict__ bc_w)
{
    extern __shared__ __align__(128) char smem[];
    const int b = blockIdx.x;
    if (b < 512) {
        const int bm = (b & 31) * BM;
        const int yy = b >> 5;
        const int bn = (yy & 7) * BN;
        float acc[4][4][4];
        if (yy < 8) {
            gemm_mainloop(Xh, W1, DM, bm, bn, smem_u32(smem), acc);
            gemm_epilogue<0>(acc, nullptr, g_u, bm, bn, DM);
        } else {
            gemm_mainloop(Xh, W2, DM, bm, bn, smem_u32(smem), acc);
            gemm_epilogue<1>(acc, dt_b, g_dt, bm, bn, DM);
        }
    } else {
        // bc weight fp32 -> fp16 (backfills SMs as GEMM waves drain)
        const int pb = b - 512;
        const int base = pb * 16384;                 // float4 units
#pragma unroll 4
        for (int k = 0; k < 64; k++) {
            const int i = (base + k * NTHREADS + threadIdx.x) * 4;
            float4 v = *(const float4*)(bc_w + i);
            __half2* dp = (__half2*)(g_wbch + i);
            dp[0] = __floats2half2_rn(v.x, v.y);
            dp[1] = __floats2half2_rn(v.z, v.w);
        }
    }
}

// ---------------- out projection GEMM ---------------------------------------
__global__ void __launch_bounds__(NTHREADS, 2)
gemm_out(const __half* __restrict__ Zh, const __half* __restrict__ Wo,
         const float* __restrict__ out_b, float* __restrict__ Out)
{
    extern __shared__ __align__(128) char smem[];
    const int bm = blockIdx.x * BM, bn = blockIdx.y * BN;
    float acc[4][4][4];
    gemm_mainloop(Zh, Wo, DM, bm, bn, smem_u32(smem), acc);
    gemm_epilogue<2>(acc, out_b, Out, bm, bn, DM);
}

// ---------------- fused bc GEMM + SSM state update --------------------------
// Warp's 32 N-cols = one d-channel's [B(16)|C(16)]; quad shfl-reduce y.
__global__ void __launch_bounds__(NTHREADS, 2)
mamba_tc(const __half* __restrict__ A, const __half* __restrict__ W,
         const float* __restrict__ H, const float* __restrict__ Dp,
         float* __restrict__ Hout)
{
    extern __shared__ __align__(128) char smem[];
    const int bm = blockIdx.x * BM, bn = blockIdx.y * BN;
    float acc[4][4][4];
    gemm_mainloop(A, W, DM, bm, bn, smem_u32(smem), acc);

    const int lane = threadIdx.x & 31, wid = threadIdx.x >> 5;
    const int wm = wid >> 2, wn = wid & 3;
    const int q = lane >> 2, c = lane & 3;
    const int dg = (bn >> 5) + wn;
    const int s0 = 2 * c;

    const float An0 = g_An[dg * DS + s0],     An1 = g_An[dg * DS + s0 + 1];
    const float An2 = g_An[dg * DS + s0 + 8], An3 = g_An[dg * DS + s0 + 9];
    const float dc = Dp[dg];

#pragma unroll
    for (int mt = 0; mt < 4; mt++) {
#pragma unroll
        for (int hf = 0; hf < 2; hf++) {
            const int bg = bm + wm * 64 + mt * 16 + q + 8 * hf;
            const float u  = g_u [(size_t)bg * DM + dg];
            const float dt = g_dt[(size_t)bg * DM + dg];
            const float Bv0 = acc[mt][0][2 * hf], Bv1 = acc[mt][0][2 * hf + 1];
            const float Bv2 = acc[mt][1][2 * hf], Bv3 = acc[mt][1][2 * hf + 1];
            const float Cv0 = acc[mt][2][2 * hf], Cv1 = acc[mt][2][2 * hf + 1];
            const float Cv2 = acc[mt][3][2 * hf], Cv3 = acc[mt][3][2 * hf + 1];

            const float* hp = H + ((size_t)bg * DM + dg) * DS;
            const float2 ha = *(const float2*)(hp + s0);
            const float2 hb = *(const float2*)(hp + 8 + s0);

            const float du = dt * u;
            const float h0 = __expf(dt * An0) * ha.x + du * Bv0;
            const float h1 = __expf(dt * An1) * ha.y + du * Bv1;
            const float h2 = __expf(dt * An2) * hb.x + du * Bv2;
            const float h3 = __expf(dt * An3) * hb.y + du * Bv3;

            float* ho = Hout + ((size_t)bg * DM + dg) * DS;
            *(float2*)(ho + s0)     = make_float2(h0, h1);
            *(float2*)(ho + 8 + s0) = make_float2(h2, h3);

            float y = h0 * Cv0 + h1 * Cv1 + h2 * Cv2 + h3 * Cv3;
            y += __shfl_xor_sync(0xffffffffu, y, 1);
            y += __shfl_xor_sync(0xffffffffu, y, 2);
            if (c == 0) {
                y = fmaf(dc, u, y);
                const float z = y / (1.f + __expf(-y));
                g_zh[(size_t)bg * DM + dg] = __float2half_rn(z);
            }
        }
    }
}

// ---------------- prep1: x + square weights + A -----------------------------
// Blocks: [0,4096) x ; [4096,5120) w1 ; [5120,6144) w2 ; [6144,7168) wo ;
// [7168,7232) A_log.
#define PB_X (NB * DM / 1024)        // 4096
#define PB_W (DM * DM / 1024)        // 1024

__device__ __forceinline__ void cvt4(const float* __restrict__ s,
                                     __half* __restrict__ d, int i) {
    float4 v = *(const float4*)(s + i);
    __half2* dp = (__half2*)(d + i);
    dp[0] = __floats2half2_rn(v.x, v.y);
    dp[1] = __floats2half2_rn(v.z, v.w);
}
__global__ void prep1(const float* __restrict__ x,
                      const float* __restrict__ w1,
                      const float* __restrict__ w2,
                      const float* __restrict__ wo,
                      const float* __restrict__ A_log) {
    int b = blockIdx.x;
    if (b < PB_X) {
        cvt4(x, g_xh, (b * 256 + threadIdx.x) * 4);
    } else if (b < PB_X + PB_W) {
        cvt4(w1, g_w1h, ((b - PB_X) * 256 + threadIdx.x) * 4);
    } else if (b < PB_X + 2 * PB_W) {
        cvt4(w2, g_w2h, ((b - PB_X - PB_W) * 256 + threadIdx.x) * 4);
    } else if (b < PB_X + 3 * PB_W) {
        cvt4(wo, g_woh, ((b - PB_X - 2 * PB_W) * 256 + threadIdx.x) * 4);
    } else {
        int i = (b - PB_X - 3 * PB_W) * 256 + threadIdx.x;
        if (i < DM * DS) g_An[i] = -__expf(A_log[i]);
    }
}

// ---------------- launch -----------------------------------------------------
extern "C" void kernel_launch(void* const* d_in, const int* in_sizes, int n_in,
                              void* d_out, int out_size)
{
    const float* x     = (const float*)d_in[0];
    const float* h     = (const float*)d_in[1];
    const float* in_w  = (const float*)d_in[2];
    const float* dt_w  = (const float*)d_in[3];
    const float* dt_b  = (const float*)d_in[4];
    const float* bc_w  = (const float*)d_in[5];
    const float* A_log = (const float*)d_in[6];
    const float* Dp    = (const float*)d_in[7];
    const float* out_w = (const float*)d_in[8];
    const float* out_b = (const float*)d_in[9];

    float* out  = (float*)d_out;
    float* hout = out + (size_t)NB * DM;

    __half *p_xh, *p_w1, *p_w2, *p_wo, *p_wbc, *p_zh;
    cudaGetSymbolAddress((void**)&p_xh,  g_xh);
    cudaGetSymbolAddress((void**)&p_w1,  g_w1h);
    cudaGetSymbolAddress((void**)&p_w2,  g_w2h);
    cudaGetSymbolAddress((void**)&p_wo,  g_woh);
    cudaGetSymbolAddress((void**)&p_wbc, g_wbch);
    cudaGetSymbolAddress((void**)&p_zh,  g_zh);

    cudaFuncSetAttribute(gemm_dual, cudaFuncAttributeMaxDynamicSharedMemorySize, SMEM_BYTES);
    cudaFuncSetAttribute(gemm_out,  cudaFuncAttributeMaxDynamicSharedMemorySize, SMEM_BYTES);
    cudaFuncSetAttribute(mamba_tc,  cudaFuncAttributeMaxDynamicSharedMemorySize, SMEM_BYTES);

    // L1: x + square weights + A
    prep1<<<PB_X + 3 * PB_W + 64, 256>>>(x, in_w, dt_w, out_w, A_log);

    // L2: u/dt GEMMs + bc weight conversion in one launch
    gemm_dual<<<512 + PREP_BC_BLOCKS, NTHREADS, SMEM_BYTES>>>(p_xh, p_w1, p_w2, dt_b, bc_w);

    // L3: fused bc GEMM + SSM update
    dim3 gbc(NB / BM, NBC / BN);         // (32, 256)
    mamba_tc<<<gbc, NTHREADS, SMEM_BYTES>>>(p_xh, p_wbc, h, Dp, hout);

    // L4: out projection
    dim3 gsq(NB / BM, DM / BN);          // (32, 8)
    gemm_out<<<gsq, NTHREADS, SMEM_BYTES>>>(p_zh, p_wo, out_b, out);
}